// round 2
// baseline (speedup 1.0000x reference)
#include <cuda_runtime.h>

#define BATCH 512
#define NROWS 256
#define NVECS 8
#define VEC   128
#define DIM   1024
#define EPSF  1e-8f

// Scratch (device globals: allocation-free per harness rules)
__device__ float g_cos[BATCH * NROWS * NVECS];   // relu'd cosine sims [b][r][n]
__device__ float g_qinv[BATCH * NVECS];          // 1/max(||q_seg||, eps)
__device__ float g_winv[NROWS * NVECS];          // 1/max(||w_seg||, eps)

// ---------------------------------------------------------------------------
// Kernel 0: per-(row, segment) inverse norms. 768 blocks x 256 threads.
// Warp w of each block handles segment w of its row.
// ---------------------------------------------------------------------------
__global__ void norm_kernel(const float* __restrict__ query,
                            const float* __restrict__ weight) {
    int row  = blockIdx.x;            // 0..BATCH+NROWS-1
    int seg  = threadIdx.x >> 5;      // 0..7
    int lane = threadIdx.x & 31;

    const float* base;
    float* dst;
    if (row < BATCH) {
        base = query + (size_t)row * DIM;
        dst  = g_qinv + row * NVECS;
    } else {
        base = weight + (size_t)(row - BATCH) * DIM;
        dst  = g_winv + (row - BATCH) * NVECS;
    }
    const float* p = base + seg * VEC;
    float s = 0.0f;
#pragma unroll
    for (int i = 0; i < 4; i++) {
        float v = p[lane + 32 * i];
        s = fmaf(v, v, s);
    }
#pragma unroll
    for (int o = 16; o > 0; o >>= 1)
        s += __shfl_xor_sync(0xffffffffu, s, o);
    if (lane == 0)
        dst[seg] = 1.0f / fmaxf(sqrtf(s), EPSF);
}

// ---------------------------------------------------------------------------
// Kernel 1: segmented GEMM -> relu'd cosine sims.
// BM=BR=64, 256 threads (16x16), 4x4 micro-tile, one segment per blockIdx.z.
// Smem stride VEC+1=129 makes ws[tx + 16j][k] conflict-free (bank = tx mod 32)
// and qs reads broadcast/adjacent-bank.
// ---------------------------------------------------------------------------
#define BM 64
#define BR 64

__global__ __launch_bounds__(256) void dot_kernel(const float* __restrict__ query,
                                                  const float* __restrict__ weight) {
    __shared__ float qs[BM][VEC + 1];
    __shared__ float ws[BR][VEC + 1];

    int seg   = blockIdx.z;
    int bbase = blockIdx.x * BM;
    int rbase = blockIdx.y * BR;
    int tid   = threadIdx.x;
    int tx    = tid & 15;
    int ty    = tid >> 4;

    // Cooperative tile loads: 64 rows x 128 floats each (float4 from gmem).
    for (int i = tid; i < BM * (VEC / 4); i += 256) {
        int row = i >> 5;          // 32 float4 per row
        int c4  = i & 31;
        float4 v = *(const float4*)(query + (size_t)(bbase + row) * DIM + seg * VEC + c4 * 4);
        qs[row][c4 * 4 + 0] = v.x;
        qs[row][c4 * 4 + 1] = v.y;
        qs[row][c4 * 4 + 2] = v.z;
        qs[row][c4 * 4 + 3] = v.w;
    }
    for (int i = tid; i < BR * (VEC / 4); i += 256) {
        int row = i >> 5;
        int c4  = i & 31;
        float4 v = *(const float4*)(weight + (size_t)(rbase + row) * DIM + seg * VEC + c4 * 4);
        ws[row][c4 * 4 + 0] = v.x;
        ws[row][c4 * 4 + 1] = v.y;
        ws[row][c4 * 4 + 2] = v.z;
        ws[row][c4 * 4 + 3] = v.w;
    }
    __syncthreads();

    float acc[4][4] = {};
#pragma unroll 4
    for (int k = 0; k < VEC; k++) {
        float qv[4], wv[4];
#pragma unroll
        for (int i = 0; i < 4; i++) qv[i] = qs[ty + 16 * i][k];
#pragma unroll
        for (int j = 0; j < 4; j++) wv[j] = ws[tx + 16 * j][k];
#pragma unroll
        for (int i = 0; i < 4; i++)
#pragma unroll
            for (int j = 0; j < 4; j++)
                acc[i][j] = fmaf(qv[i], wv[j], acc[i][j]);
    }

#pragma unroll
    for (int i = 0; i < 4; i++) {
        int b = bbase + ty + 16 * i;
        float qi = g_qinv[b * NVECS + seg];
#pragma unroll
        for (int j = 0; j < 4; j++) {
            int r = rbase + tx + 16 * j;
            float v = acc[i][j] * qi * g_winv[r * NVECS + seg];
            g_cos[((size_t)b * NROWS + r) * NVECS + seg] = fmaxf(v, 0.0f);
        }
    }
}

// ---------------------------------------------------------------------------
// Kernel 2: exhaustive combo-product expansion. One block per batch row.
// Each thread produces 4 adjacent combos per r (shared 6-term tail product),
// one float4 store -> fully coalesced 128 MiB of output.
// combo i, bit j: bit==0 -> cs_j, bit==1 -> (1 - cs_j); output = prod_j.
// ---------------------------------------------------------------------------
__global__ __launch_bounds__(256) void combo_kernel(float* __restrict__ out) {
    __shared__ float cs[NROWS * NVECS];   // 8 KB: all 256 r-rows' 8 cos values

    int b   = blockIdx.x;
    int tid = threadIdx.x;

    const float* src = g_cos + (size_t)b * NROWS * NVECS;
    for (int i = tid; i < NROWS * NVECS / 4; i += 256)
        ((float4*)cs)[i] = ((const float4*)src)[i];
    __syncthreads();

    int sub   = tid & 63;   // combo group: combos [4*sub, 4*sub+3]
    int rlane = tid >> 6;   // 0..3
    float* ob = out + (size_t)b * NROWS * 256;

#pragma unroll 4
    for (int rg = 0; rg < 64; rg++) {
        int r = rg * 4 + rlane;
        const float* c = cs + r * NVECS;

        // tail product over bits 2..7 (sub's bits 0..5)
        float p = 1.0f;
#pragma unroll
        for (int j = 2; j < 8; j++) {
            float v = c[j];
            p *= ((sub >> (j - 2)) & 1) ? (1.0f - v) : v;
        }
        float c0 = c[0], c1 = c[1];
        float pc1  = p * c1;
        float pn1  = p * (1.0f - c1);
        float4 o;
        o.x = pc1 * c0;            // k=0: bits (0,0)
        o.y = pc1 * (1.0f - c0);   // k=1: bits (1,0)
        o.z = pn1 * c0;            // k=2: bits (0,1)
        o.w = pn1 * (1.0f - c0);   // k=3: bits (1,1)

        ((float4*)(ob + (size_t)r * 256))[sub] = o;
    }
}

// ---------------------------------------------------------------------------
extern "C" void kernel_launch(void* const* d_in, const int* in_sizes, int n_in,
                              void* d_out, int out_size) {
    const float* query  = (const float*)d_in[0];   // [512, 1024]
    const float* weight = (const float*)d_in[1];   // [256, 1024]
    float* out = (float*)d_out;                    // [512, 256, 256]

    norm_kernel<<<BATCH + NROWS, 256>>>(query, weight);
    dot_kernel<<<dim3(BATCH / BM, NROWS / BR, NVECS), 256>>>(query, weight);
    combo_kernel<<<BATCH, 256>>>(out);
}

// round 3
// speedup vs baseline: 1.0736x; 1.0736x over previous
#include <cuda_runtime.h>

#define BATCH 512
#define NROWS 256
#define NVECS 8
#define VEC   128
#define DIM   1024
#define EPSF  1e-8f

// Scratch: relu'd cosine sims, layout [seg][b][r] for coalesced GEMM-epilogue
// stores and contiguous combo reads.
__device__ float g_cos[NVECS * BATCH * NROWS];

// ---------------------------------------------------------------------------
// Kernel 1: segmented GEMM + fused per-segment norms -> relu'd cosine sims.
// BM=BR=64, 256 threads (16x16), 4x4 micro-tile, one segment per blockIdx.z.
// Norms computed from the smem tiles (threads 0..127) — no separate kernel.
// ---------------------------------------------------------------------------
#define BM 64
#define BR 64

__global__ __launch_bounds__(256) void dot_kernel(const float* __restrict__ query,
                                                  const float* __restrict__ weight) {
    __shared__ float qs[BM][VEC + 1];
    __shared__ float ws[BR][VEC + 1];
    __shared__ float qn[BM];
    __shared__ float wn[BR];

    int seg   = blockIdx.z;
    int bbase = blockIdx.x * BM;
    int rbase = blockIdx.y * BR;
    int tid   = threadIdx.x;
    int tx    = tid & 15;
    int ty    = tid >> 4;

    // Cooperative tile loads: 64 rows x 128 floats each (float4 from gmem).
    for (int i = tid; i < BM * (VEC / 4); i += 256) {
        int row = i >> 5;          // 32 float4 per row
        int c4  = i & 31;
        float4 v = *(const float4*)(query + (size_t)(bbase + row) * DIM + seg * VEC + c4 * 4);
        qs[row][c4 * 4 + 0] = v.x;
        qs[row][c4 * 4 + 1] = v.y;
        qs[row][c4 * 4 + 2] = v.z;
        qs[row][c4 * 4 + 3] = v.w;
    }
    for (int i = tid; i < BR * (VEC / 4); i += 256) {
        int row = i >> 5;
        int c4  = i & 31;
        float4 v = *(const float4*)(weight + (size_t)(rbase + row) * DIM + seg * VEC + c4 * 4);
        ws[row][c4 * 4 + 0] = v.x;
        ws[row][c4 * 4 + 1] = v.y;
        ws[row][c4 * 4 + 2] = v.z;
        ws[row][c4 * 4 + 3] = v.w;
    }
    __syncthreads();

    // Fused inverse norms from smem tiles. Addr row*129+k -> banks (row+k)%32:
    // conflict-free across consecutive-row lanes.
    if (tid < BM) {
        float s = 0.0f;
#pragma unroll 8
        for (int k = 0; k < VEC; k++) s = fmaf(qs[tid][k], qs[tid][k], s);
        qn[tid] = 1.0f / fmaxf(sqrtf(s), EPSF);
    } else if (tid < BM + BR) {
        int row = tid - BM;
        float s = 0.0f;
#pragma unroll 8
        for (int k = 0; k < VEC; k++) s = fmaf(ws[row][k], ws[row][k], s);
        wn[row] = 1.0f / fmaxf(sqrtf(s), EPSF);
    }
    __syncthreads();

    float acc[4][4] = {};
#pragma unroll 4
    for (int k = 0; k < VEC; k++) {
        float qv[4], wv[4];
#pragma unroll
        for (int i = 0; i < 4; i++) qv[i] = qs[ty + 16 * i][k];
#pragma unroll
        for (int j = 0; j < 4; j++) wv[j] = ws[tx + 16 * j][k];
#pragma unroll
        for (int i = 0; i < 4; i++)
#pragma unroll
            for (int j = 0; j < 4; j++)
                acc[i][j] = fmaf(qv[i], wv[j], acc[i][j]);
    }

    // Epilogue: scale, relu, store to [seg][b][r] (r-contiguous -> coalesced).
    float* dst = g_cos + (size_t)seg * BATCH * NROWS;
#pragma unroll
    for (int i = 0; i < 4; i++) {
        int b = bbase + ty + 16 * i;
        float qi = qn[ty + 16 * i];
#pragma unroll
        for (int j = 0; j < 4; j++) {
            int r = rbase + tx + 16 * j;
            float v = acc[i][j] * qi * wn[tx + 16 * j];
            dst[(size_t)b * NROWS + r] = fmaxf(v, 0.0f);
        }
    }
}

// ---------------------------------------------------------------------------
// Kernel 2: exhaustive combo-product expansion.
// 2048 CTAs: blockIdx -> (b, 64-row r-chunk) for fine wave granularity.
// Each thread: 4 adjacent combos (shared 6-term tail) per r, float4 store.
// Select (bit? 1-v : v) == fmaf(sgn, v, off) with precomputed sgn/off.
// ---------------------------------------------------------------------------
#define RCHUNK 64

__global__ __launch_bounds__(256) void combo_kernel(float* __restrict__ out) {
    __shared__ float cs[RCHUNK][NVECS];   // 2 KB

    int b   = blockIdx.x >> 2;
    int r0  = (blockIdx.x & 3) * RCHUNK;
    int tid = threadIdx.x;

    // Load this chunk's cos values: 8 contiguous 256B runs (one per seg).
    for (int i = tid; i < RCHUNK * NVECS; i += 256) {
        int seg = i >> 6;         // 0..7
        int rr  = i & 63;
        cs[rr][seg] = g_cos[(size_t)seg * BATCH * NROWS + (size_t)b * NROWS + r0 + rr];
    }
    __syncthreads();

    int sub   = tid & 63;   // combo quad: combos [4*sub, 4*sub+3]
    int rlane = tid >> 6;   // 0..3

    // Per-bit select constants for tail bits j=2..7 (sub bits 0..5).
    float sgn[6], off[6];
#pragma unroll
    for (int j = 0; j < 6; j++) {
        int bit = (sub >> j) & 1;
        sgn[j] = bit ? -1.0f : 1.0f;
        off[j] = bit ? 1.0f : 0.0f;
    }

    float* ob = out + (size_t)b * NROWS * 256 + (size_t)r0 * 256;

#pragma unroll
    for (int rg = 0; rg < RCHUNK / 4; rg++) {
        int r = rg * 4 + rlane;
        const float* c = cs[r];

        float t2 = fmaf(sgn[0], c[2], off[0]);
        float t3 = fmaf(sgn[1], c[3], off[1]);
        float t4 = fmaf(sgn[2], c[4], off[2]);
        float t5 = fmaf(sgn[3], c[5], off[3]);
        float t6 = fmaf(sgn[4], c[6], off[4]);
        float t7 = fmaf(sgn[5], c[7], off[5]);
        float p  = ((t2 * t3) * (t4 * t5)) * (t6 * t7);

        float c0 = c[0], c1 = c[1];
        float n0 = 1.0f - c0;
        float pc1 = p * c1;
        float pn1 = p * (1.0f - c1);
        float4 o;
        o.x = pc1 * c0;    // combo bits (0,0)
        o.y = pc1 * n0;    // (1,0)
        o.z = pn1 * c0;    // (0,1)
        o.w = pn1 * n0;    // (1,1)

        ((float4*)(ob + (size_t)r * 256))[sub] = o;
    }
}

// ---------------------------------------------------------------------------
extern "C" void kernel_launch(void* const* d_in, const int* in_sizes, int n_in,
                              void* d_out, int out_size) {
    const float* query  = (const float*)d_in[0];   // [512, 1024]
    const float* weight = (const float*)d_in[1];   // [256, 1024]
    float* out = (float*)d_out;                    // [512, 256, 256]

    dot_kernel<<<dim3(BATCH / BM, NROWS / BR, NVECS), 256>>>(query, weight);
    combo_kernel<<<BATCH * (NROWS / RCHUNK), 256>>>(out);
}

// round 4
// speedup vs baseline: 1.1089x; 1.0328x over previous
#include <cuda_runtime.h>

#define BATCH 512
#define NROWS 256
#define NVECS 8
#define VEC   128
#define DIM   1024
#define EPSF  1e-8f

// Scratch: relu'd cosine sims, layout [seg][b][r].
__device__ float g_cos[NVECS * BATCH * NROWS];

// ---------------------------------------------------------------------------
// Kernel 1: segmented GEMM + fused per-segment norms -> relu'd cosine sims.
// BM=BR=64, 256 threads (16x16), 4x4 micro-tile, seg = blockIdx.z.
// Row stride VEC+4=132 keeps float4 smem reads 16B-aligned -> LDS.128.
// ---------------------------------------------------------------------------
#define BM 64
#define BR 64
#define LDP (VEC + 4)

__global__ __launch_bounds__(256) void dot_kernel(const float* __restrict__ query,
                                                  const float* __restrict__ weight) {
    __shared__ float qs[BM][LDP];
    __shared__ float ws[BR][LDP];
    __shared__ float qn[BM];
    __shared__ float wn[BR];

    int seg   = blockIdx.z;
    int bbase = blockIdx.x * BM;
    int rbase = blockIdx.y * BR;
    int tid   = threadIdx.x;
    int tx    = tid & 15;
    int ty    = tid >> 4;

    // Cooperative tile loads (float4 from gmem, float4 to smem).
    for (int i = tid; i < BM * (VEC / 4); i += 256) {
        int row = i >> 5;          // 32 float4 per row
        int c4  = i & 31;
        float4 v = *(const float4*)(query + (size_t)(bbase + row) * DIM + seg * VEC + c4 * 4);
        *(float4*)&qs[row][c4 * 4] = v;
    }
    for (int i = tid; i < BR * (VEC / 4); i += 256) {
        int row = i >> 5;
        int c4  = i & 31;
        float4 v = *(const float4*)(weight + (size_t)(rbase + row) * DIM + seg * VEC + c4 * 4);
        *(float4*)&ws[row][c4 * 4] = v;
    }
    __syncthreads();

    // Fused inverse norms from smem tiles (vectorized).
    if (tid < BM) {
        float s = 0.0f;
#pragma unroll 8
        for (int k = 0; k < VEC; k += 4) {
            float4 v = *(const float4*)&qs[tid][k];
            s = fmaf(v.x, v.x, s); s = fmaf(v.y, v.y, s);
            s = fmaf(v.z, v.z, s); s = fmaf(v.w, v.w, s);
        }
        qn[tid] = 1.0f / fmaxf(sqrtf(s), EPSF);
    } else if (tid < BM + BR) {
        int row = tid - BM;
        float s = 0.0f;
#pragma unroll 8
        for (int k = 0; k < VEC; k += 4) {
            float4 v = *(const float4*)&ws[row][k];
            s = fmaf(v.x, v.x, s); s = fmaf(v.y, v.y, s);
            s = fmaf(v.z, v.z, s); s = fmaf(v.w, v.w, s);
        }
        wn[row] = 1.0f / fmaxf(sqrtf(s), EPSF);
    }
    __syncthreads();

    float acc[4][4] = {};
#pragma unroll 2
    for (int k = 0; k < VEC; k += 4) {
        float4 qv[4], wv[4];
#pragma unroll
        for (int i = 0; i < 4; i++) qv[i] = *(const float4*)&qs[ty + 16 * i][k];
#pragma unroll
        for (int j = 0; j < 4; j++) wv[j] = *(const float4*)&ws[tx + 16 * j][k];
#pragma unroll
        for (int i = 0; i < 4; i++)
#pragma unroll
            for (int j = 0; j < 4; j++) {
                acc[i][j] = fmaf(qv[i].x, wv[j].x, acc[i][j]);
                acc[i][j] = fmaf(qv[i].y, wv[j].y, acc[i][j]);
                acc[i][j] = fmaf(qv[i].z, wv[j].z, acc[i][j]);
                acc[i][j] = fmaf(qv[i].w, wv[j].w, acc[i][j]);
            }
    }

    // Epilogue: scale, relu, store to [seg][b][r] (r-contiguous -> coalesced).
    float* dst = g_cos + (size_t)seg * BATCH * NROWS;
#pragma unroll
    for (int i = 0; i < 4; i++) {
        int b = bbase + ty + 16 * i;
        float qi = qn[ty + 16 * i];
#pragma unroll
        for (int j = 0; j < 4; j++) {
            int r = rbase + tx + 16 * j;
            float v = acc[i][j] * qi * wn[tx + 16 * j];
            dst[(size_t)b * NROWS + r] = fmaxf(v, 0.0f);
        }
    }
}

// ---------------------------------------------------------------------------
// Kernel 2: exhaustive combo-product expansion.
// 2048 CTAs: blockIdx -> (b, 64-row r-chunk). Each thread produces 8 combos
// per r: shared 5-term tail (combo bits 2..6 from lane), split on bit 7 into
// two contiguous-per-warp float4 stores (combo quads sub5 and sub5+32).
// ---------------------------------------------------------------------------
#define RCHUNK 64

__global__ __launch_bounds__(256) void combo_kernel(float* __restrict__ out) {
    __shared__ float cs[RCHUNK][NVECS];   // 2 KB

    int b   = blockIdx.x >> 2;
    int r0  = (blockIdx.x & 3) * RCHUNK;
    int tid = threadIdx.x;

    // Load this chunk's cos values: 8 contiguous 256B runs (one per seg).
    for (int i = tid; i < RCHUNK * NVECS; i += 256) {
        int seg = i >> 6;         // 0..7
        int rr  = i & 63;
        cs[rr][seg] = g_cos[(size_t)seg * BATCH * NROWS + (size_t)b * NROWS + r0 + rr];
    }
    __syncthreads();

    int sub5  = tid & 31;   // combo bits 2..6
    int rlane = tid >> 5;   // 0..7

    // Per-bit select constants: (bit? 1-v : v) == fmaf(sgn, v, off).
    float sgn[5], off[5];
#pragma unroll
    for (int j = 0; j < 5; j++) {
        int bit = (sub5 >> j) & 1;
        sgn[j] = bit ? -1.0f : 1.0f;
        off[j] = bit ? 1.0f : 0.0f;
    }

    float* ob = out + (size_t)b * NROWS * 256 + (size_t)r0 * 256;

#pragma unroll
    for (int rg = 0; rg < RCHUNK / 8; rg++) {
        int r = rg * 8 + rlane;
        const float* c = cs[r];

        // tail over combo bits 2..6
        float t2 = fmaf(sgn[0], c[2], off[0]);
        float t3 = fmaf(sgn[1], c[3], off[1]);
        float t4 = fmaf(sgn[2], c[4], off[2]);
        float t5 = fmaf(sgn[3], c[5], off[3]);
        float t6 = fmaf(sgn[4], c[6], off[4]);
        float p5 = ((t2 * t3) * (t4 * t5)) * t6;

        float c7 = c[7];
        float pA = p5 * c7;            // combo bit7 = 0
        float pB = p5 * (1.0f - c7);   // combo bit7 = 1

        float c0 = c[0], c1 = c[1];
        float n0 = 1.0f - c0;
        float n1 = 1.0f - c1;

        float pA1 = pA * c1, pAn = pA * n1;
        float pB1 = pB * c1, pBn = pB * n1;

        float4 oA, oB;
        oA.x = pA1 * c0;  oA.y = pA1 * n0;  oA.z = pAn * c0;  oA.w = pAn * n0;
        oB.x = pB1 * c0;  oB.y = pB1 * n0;  oB.z = pBn * c0;  oB.w = pBn * n0;

        float4* orow = (float4*)(ob + (size_t)r * 256);
        orow[sub5]      = oA;   // combos [4*sub5, 4*sub5+3]
        orow[sub5 + 32] = oB;   // combos [128+4*sub5, 128+4*sub5+3]
    }
}

// ---------------------------------------------------------------------------
extern "C" void kernel_launch(void* const* d_in, const int* in_sizes, int n_in,
                              void* d_out, int out_size) {
    const float* query  = (const float*)d_in[0];   // [512, 1024]
    const float* weight = (const float*)d_in[1];   // [256, 1024]
    float* out = (float*)d_out;                    // [512, 256, 256]

    dot_kernel<<<dim3(BATCH / BM, NROWS / BR, NVECS), 256>>>(query, weight);
    combo_kernel<<<BATCH * (NROWS / RCHUNK), 256>>>(out);
}

// round 9
// speedup vs baseline: 1.2109x; 1.0920x over previous
#include <cuda_runtime.h>

#define BATCH 512
#define NROWS 256
#define NVECS 8
#define VEC   128
#define DIM   1024
#define EPSF  1e-8f

// Scratch: relu'd cosine sims, layout [seg][b][r].
__device__ float g_cos[NVECS * BATCH * NROWS];

// ---------------------------------------------------------------------------
// Kernel 1: segmented GEMM + fused per-segment norms -> relu'd cosine sims.
// BM=128, BR=64, 512 threads (16x32), 4x4 micro-tile, seg = blockIdx.z.
// grid = 4*4*8 = 128 CTAs <= 148 SMs: SINGLE WAVE (no wave quantization).
// qs unpadded (warp reads are 2-address broadcast); ws padded +4 floats so
// the 16 distinct float4 row-reads per warp spread across banks (2-way max).
// ~100 KB dynamic smem (needs cudaFuncSetAttribute).
// ---------------------------------------------------------------------------
#define BM 128
#define BR 64
#define WPAD (VEC + 4)

__global__ __launch_bounds__(512) void dot_kernel(const float* __restrict__ query,
                                                  const float* __restrict__ weight) {
    extern __shared__ float smem[];
    float (*qs)[VEC]  = (float (*)[VEC])smem;                  // 128 x 128
    float (*ws)[WPAD] = (float (*)[WPAD])(smem + BM * VEC);    // 64 x 132
    float* qn = smem + BM * VEC + BR * WPAD;                   // 128
    float* wn = qn + BM;                                       // 64

    int seg   = blockIdx.z;
    int bbase = blockIdx.x * BM;
    int rbase = blockIdx.y * BR;
    int tid   = threadIdx.x;
    int tx    = tid & 15;    // r micro-index
    int ty    = tid >> 4;    // b micro-index (0..31)

    // Cooperative tile loads (float4 gmem -> float4 smem).
    for (int i = tid; i < BM * (VEC / 4); i += 512) {
        int row = i >> 5;          // 32 float4 per row
        int c4  = i & 31;
        float4 v = *(const float4*)(query + (size_t)(bbase + row) * DIM + seg * VEC + c4 * 4);
        *(float4*)&qs[row][c4 * 4] = v;
    }
    for (int i = tid; i < BR * (VEC / 4); i += 512) {
        int row = i >> 5;
        int c4  = i & 31;
        float4 v = *(const float4*)(weight + (size_t)(rbase + row) * DIM + seg * VEC + c4 * 4);
        *(float4*)&ws[row][c4 * 4] = v;
    }
    __syncthreads();

    // Fused inverse norms from smem tiles (vectorized).
    if (tid < BM) {
        float s = 0.0f;
#pragma unroll 8
        for (int k = 0; k < VEC; k += 4) {
            float4 v = *(const float4*)&qs[tid][k];
            s = fmaf(v.x, v.x, s); s = fmaf(v.y, v.y, s);
            s = fmaf(v.z, v.z, s); s = fmaf(v.w, v.w, s);
        }
        qn[tid] = 1.0f / fmaxf(sqrtf(s), EPSF);
    } else if (tid < BM + BR) {
        int row = tid - BM;
        float s = 0.0f;
#pragma unroll 8
        for (int k = 0; k < VEC; k += 4) {
            float4 v = *(const float4*)&ws[row][k];
            s = fmaf(v.x, v.x, s); s = fmaf(v.y, v.y, s);
            s = fmaf(v.z, v.z, s); s = fmaf(v.w, v.w, s);
        }
        wn[row] = 1.0f / fmaxf(sqrtf(s), EPSF);
    }
    __syncthreads();

    float acc[4][4] = {};
#pragma unroll 2
    for (int k = 0; k < VEC; k += 4) {
        float4 qv[4], wv[4];
#pragma unroll
        for (int i = 0; i < 4; i++) qv[i] = *(const float4*)&qs[ty + 32 * i][k];
#pragma unroll
        for (int j = 0; j < 4; j++) wv[j] = *(const float4*)&ws[tx + 16 * j][k];
#pragma unroll
        for (int i = 0; i < 4; i++)
#pragma unroll
            for (int j = 0; j < 4; j++) {
                acc[i][j] = fmaf(qv[i].x, wv[j].x, acc[i][j]);
                acc[i][j] = fmaf(qv[i].y, wv[j].y, acc[i][j]);
                acc[i][j] = fmaf(qv[i].z, wv[j].z, acc[i][j]);
                acc[i][j] = fmaf(qv[i].w, wv[j].w, acc[i][j]);
            }
    }

    // Epilogue: scale, relu, store to [seg][b][r] (r-contiguous -> coalesced).
    float* dst = g_cos + (size_t)seg * BATCH * NROWS;
#pragma unroll
    for (int i = 0; i < 4; i++) {
        int b = bbase + ty + 32 * i;
        float qi = qn[ty + 32 * i];
#pragma unroll
        for (int j = 0; j < 4; j++) {
            int r = rbase + tx + 16 * j;
            float v = acc[i][j] * qi * wn[tx + 16 * j];
            dst[(size_t)b * NROWS + r] = fmaxf(v, 0.0f);
        }
    }
}

// ---------------------------------------------------------------------------
// Kernel 2: exhaustive combo-product expansion.
// 2048 CTAs: blockIdx -> (b, 64-row r-chunk). Each thread: 4 adjacent combos
// per r (shared 6-term fmaf-select tail), one streaming float4 store (.cs:
// output is write-once, evict-first reduces L2 dirty pressure).
// ---------------------------------------------------------------------------
#define RCHUNK 64

__global__ __launch_bounds__(256) void combo_kernel(float* __restrict__ out) {
    __shared__ float cs[RCHUNK][NVECS];   // 2 KB

    int b   = blockIdx.x >> 2;
    int r0  = (blockIdx.x & 3) * RCHUNK;
    int tid = threadIdx.x;

    // Load this chunk's cos values: 8 contiguous 256B runs (one per seg).
    for (int i = tid; i < RCHUNK * NVECS; i += 256) {
        int seg = i >> 6;         // 0..7
        int rr  = i & 63;
        cs[rr][seg] = g_cos[(size_t)seg * BATCH * NROWS + (size_t)b * NROWS + r0 + rr];
    }
    __syncthreads();

    int sub   = tid & 63;   // combo quad: combos [4*sub, 4*sub+3]
    int rlane = tid >> 6;   // 0..3

    // Per-bit select constants: (bit? 1-v : v) == fmaf(sgn, v, off).
    float sgn[6], off[6];
#pragma unroll
    for (int j = 0; j < 6; j++) {
        int bit = (sub >> j) & 1;
        sgn[j] = bit ? -1.0f : 1.0f;
        off[j] = bit ? 1.0f : 0.0f;
    }

    float* ob = out + (size_t)b * NROWS * 256 + (size_t)r0 * 256;

#pragma unroll
    for (int rg = 0; rg < RCHUNK / 4; rg++) {
        int r = rg * 4 + rlane;
        const float* c = cs[r];

        float t2 = fmaf(sgn[0], c[2], off[0]);
        float t3 = fmaf(sgn[1], c[3], off[1]);
        float t4 = fmaf(sgn[2], c[4], off[2]);
        float t5 = fmaf(sgn[3], c[5], off[3]);
        float t6 = fmaf(sgn[4], c[6], off[4]);
        float t7 = fmaf(sgn[5], c[7], off[5]);
        float p  = ((t2 * t3) * (t4 * t5)) * (t6 * t7);

        float c0 = c[0], c1 = c[1];
        float n0 = 1.0f - c0;
        float pc1 = p * c1;
        float pn1 = p * (1.0f - c1);
        float4 o;
        o.x = pc1 * c0;    // combo bits (0,0)
        o.y = pc1 * n0;    // (1,0)
        o.z = pn1 * c0;    // (0,1)
        o.w = pn1 * n0;    // (1,1)

        __stcs((float4*)(ob + (size_t)r * 256) + sub, o);
    }
}

// ---------------------------------------------------------------------------
extern "C" void kernel_launch(void* const* d_in, const int* in_sizes, int n_in,
                              void* d_out, int out_size) {
    const float* query  = (const float*)d_in[0];   // [512, 1024]
    const float* weight = (const float*)d_in[1];   // [256, 1024]
    float* out = (float*)d_out;                    // [512, 256, 256]

    const int dot_smem = (BM * VEC + BR * WPAD + BM + BR) * (int)sizeof(float);
    (void)cudaFuncSetAttribute(dot_kernel,
                               cudaFuncAttributeMaxDynamicSharedMemorySize,
                               dot_smem);

    dot_kernel<<<dim3(BATCH / BM, NROWS / BR, NVECS), 512, dot_smem>>>(query, weight);
    combo_kernel<<<BATCH * (NROWS / RCHUNK), 256>>>(out);
}